// round 1
// baseline (speedup 1.0000x reference)
#include <cuda_runtime.h>
#include <cuda_bf16.h>
#include <cstdint>

#define NN 100000
#define EE 640000
#define EP 740000   /* EE + NN self loops */
#define CC 128
#define NEG_SLOPE 0.2f

// ---------------- device scratch (static allocation is the sanctioned path) --
__device__ float g_xl[(size_t)NN * CC];
__device__ float g_xr[(size_t)NN * CC];
__device__ float g_h [(size_t)NN * CC];   // layer-1 accumulator / layer-2 input
__device__ float g_ex[EP];
__device__ float g_denom[NN];

// ---------------- GEMM: out[n][c] = bias[c] + sum_k f(x[n][k]) * W[c][k] -----
// f = relu if relu_in != 0 (fuses inter-layer ReLU into the A-tile load).
// Tile: M=64, Nc=128 (full), K=128 (full). smem = As 32KB + Bs 64KB = 96KB.
// 256 threads, each computes a 4(M) x 8(N) microtile; B reads are contiguous
// float4 per lane (conflict-free), A reads broadcast.
__global__ __launch_bounds__(256) void gemm_bias_kernel(
    const float* __restrict__ x, const float* __restrict__ W,
    const float* __restrict__ bias, float* __restrict__ out, int relu_in)
{
    extern __shared__ float smem[];
    float* As = smem;            // [64][128]
    float* Bs = smem + 64 * 128; // [128][128], stored transposed: Bs[k][c] = W[c][k]

    const int tid  = threadIdx.x;
    const int row0 = blockIdx.x * 64;

    // Load W -> Bs transposed (coalesced gmem read along k)
    for (int i = tid; i < 128 * 32; i += 256) {
        int c  = i >> 5;
        int k4 = (i & 31) << 2;
        float4 w = *(const float4*)(W + c * 128 + k4);
        Bs[(k4 + 0) * 128 + c] = w.x;
        Bs[(k4 + 1) * 128 + c] = w.y;
        Bs[(k4 + 2) * 128 + c] = w.z;
        Bs[(k4 + 3) * 128 + c] = w.w;
    }
    // Load x tile -> As (optionally relu'd)
    for (int i = tid; i < 64 * 32; i += 256) {
        int m  = i >> 5;
        int k4 = (i & 31) << 2;
        int gr = row0 + m;
        float4 v = make_float4(0.f, 0.f, 0.f, 0.f);
        if (gr < NN) v = *(const float4*)(x + (size_t)gr * CC + k4);
        if (relu_in) {
            v.x = fmaxf(v.x, 0.f); v.y = fmaxf(v.y, 0.f);
            v.z = fmaxf(v.z, 0.f); v.w = fmaxf(v.w, 0.f);
        }
        *(float4*)(As + m * 128 + k4) = v;
    }
    __syncthreads();

    const int tx = tid & 15;   // -> columns tx*4 .. tx*4+3 and 64+tx*4 ..
    const int ty = tid >> 4;   // -> rows ty*4 .. ty*4+3

    float acc[4][8];
#pragma unroll
    for (int i = 0; i < 4; i++)
#pragma unroll
        for (int j = 0; j < 8; j++) acc[i][j] = 0.f;

#pragma unroll 8
    for (int k = 0; k < 128; k++) {
        float a0 = As[(ty * 4 + 0) * 128 + k];
        float a1 = As[(ty * 4 + 1) * 128 + k];
        float a2 = As[(ty * 4 + 2) * 128 + k];
        float a3 = As[(ty * 4 + 3) * 128 + k];
        float4 b0 = *(const float4*)(Bs + k * 128 + tx * 4);
        float4 b1 = *(const float4*)(Bs + k * 128 + 64 + tx * 4);
        float bb[8] = {b0.x, b0.y, b0.z, b0.w, b1.x, b1.y, b1.z, b1.w};
        float aa[4] = {a0, a1, a2, a3};
#pragma unroll
        for (int i = 0; i < 4; i++)
#pragma unroll
            for (int j = 0; j < 8; j++)
                acc[i][j] = fmaf(aa[i], bb[j], acc[i][j]);
    }

    float4 bias0 = *(const float4*)(bias + tx * 4);
    float4 bias1 = *(const float4*)(bias + 64 + tx * 4);
#pragma unroll
    for (int i = 0; i < 4; i++) {
        int gr = row0 + ty * 4 + i;
        if (gr >= NN) break;
        float4 o0 = make_float4(acc[i][0] + bias0.x, acc[i][1] + bias0.y,
                                acc[i][2] + bias0.z, acc[i][3] + bias0.w);
        float4 o1 = make_float4(acc[i][4] + bias1.x, acc[i][5] + bias1.y,
                                acc[i][6] + bias1.z, acc[i][7] + bias1.w);
        *(float4*)(out + (size_t)gr * CC + tx * 4)      = o0;
        *(float4*)(out + (size_t)gr * CC + 64 + tx * 4) = o1;
    }
}

// ---------------- edge pass 1: logits -> exp -> denom -----------------------
// One warp per edge. 512B coalesced row gathers (mostly L2-resident).
// Softmax max-shift skipped: |e| <~ 30 << 88, expf cannot overflow.
__global__ __launch_bounds__(256) void edge_logits_kernel(
    const int* __restrict__ ei, const float* __restrict__ xl,
    const float* __restrict__ xr, const float* __restrict__ att,
    float* __restrict__ ex, float* __restrict__ denom)
{
    int gw   = (int)((blockIdx.x * 256u + threadIdx.x) >> 5);
    int lane = threadIdx.x & 31;
    if (gw >= EP) return;

    int s, d;
    if (gw < EE) { s = ei[gw]; d = ei[EE + gw]; }
    else         { s = gw - EE; d = s; }

    float4 a = *(const float4*)(xl + (size_t)s * CC + lane * 4);
    float4 b = *(const float4*)(xr + (size_t)d * CC + lane * 4);
    float4 t = *(const float4*)(att + lane * 4);

    float4 m;
    m.x = a.x + b.x; m.x = m.x > 0.f ? m.x : NEG_SLOPE * m.x;
    m.y = a.y + b.y; m.y = m.y > 0.f ? m.y : NEG_SLOPE * m.y;
    m.z = a.z + b.z; m.z = m.z > 0.f ? m.z : NEG_SLOPE * m.z;
    m.w = a.w + b.w; m.w = m.w > 0.f ? m.w : NEG_SLOPE * m.w;

    float p = m.x * t.x;
    p = fmaf(m.y, t.y, p);
    p = fmaf(m.z, t.z, p);
    p = fmaf(m.w, t.w, p);

#pragma unroll
    for (int off = 16; off > 0; off >>= 1)
        p += __shfl_xor_sync(0xffffffffu, p, off);

    if (lane == 0) {
        float ev = expf(p);
        ex[gw] = ev;
        atomicAdd(denom + d, ev);
    }
}

// ---------------- edge pass 2: out[dst] += (ex/denom[dst]) * xl[src] --------
// Vectorized 16B reductions (sm_90+ red.global.add.v4.f32): 4x fewer atomics.
__global__ __launch_bounds__(256) void edge_aggr_kernel(
    const int* __restrict__ ei, const float* __restrict__ xl,
    const float* __restrict__ ex, const float* __restrict__ denom,
    float* __restrict__ acc)
{
    int gw   = (int)((blockIdx.x * 256u + threadIdx.x) >> 5);
    int lane = threadIdx.x & 31;
    if (gw >= EP) return;

    int s, d;
    if (gw < EE) { s = ei[gw]; d = ei[EE + gw]; }
    else         { s = gw - EE; d = s; }

    float alpha = 0.f;
    if (lane == 0) alpha = ex[gw] / denom[d];
    alpha = __shfl_sync(0xffffffffu, alpha, 0);

    float4 a = *(const float4*)(xl + (size_t)s * CC + lane * 4);
    float vx = alpha * a.x, vy = alpha * a.y, vz = alpha * a.z, vw = alpha * a.w;

    float* p = acc + (size_t)d * CC + lane * 4;
    asm volatile("red.global.add.v4.f32 [%0], {%1, %2, %3, %4};"
                 :: "l"(p), "f"(vx), "f"(vy), "f"(vz), "f"(vw)
                 : "memory");
}

// ---------------- launch ----------------------------------------------------
extern "C" void kernel_launch(void* const* d_in, const int* in_sizes, int n_in,
                              void* d_out, int out_size)
{
    const int*   ei    = (const int*)  d_in[0];
    const float* emb   = (const float*)d_in[1];
    const float* Wl1   = (const float*)d_in[2];
    const float* bl1   = (const float*)d_in[3];
    const float* Wr1   = (const float*)d_in[4];
    const float* br1   = (const float*)d_in[5];
    const float* att1  = (const float*)d_in[6];
    const float* Wres1 = (const float*)d_in[7];
    const float* bias1 = (const float*)d_in[8];
    const float* Wl2   = (const float*)d_in[9];
    const float* bl2   = (const float*)d_in[10];
    const float* Wr2   = (const float*)d_in[11];
    const float* br2   = (const float*)d_in[12];
    const float* att2  = (const float*)d_in[13];
    const float* Wres2 = (const float*)d_in[14];
    const float* bias2 = (const float*)d_in[15];
    float* out = (float*)d_out;

    float *xl, *xr, *h, *ex, *denom;
    cudaGetSymbolAddress((void**)&xl,    g_xl);
    cudaGetSymbolAddress((void**)&xr,    g_xr);
    cudaGetSymbolAddress((void**)&h,     g_h);
    cudaGetSymbolAddress((void**)&ex,    g_ex);
    cudaGetSymbolAddress((void**)&denom, g_denom);

    const int GEMM_SMEM = (64 * 128 + 128 * 128) * sizeof(float); // 96 KB
    cudaFuncSetAttribute(gemm_bias_kernel,
                         cudaFuncAttributeMaxDynamicSharedMemorySize, GEMM_SMEM);

    const int gemm_grid = (NN + 63) / 64;          // 1563
    const int edge_grid = (EP + 7) / 8;            // 92500 blocks of 8 warps

    // ---- layer 1 ----
    cudaMemsetAsync(denom, 0, NN * sizeof(float));
    gemm_bias_kernel<<<gemm_grid, 256, GEMM_SMEM>>>(emb, Wl1,   bl1,   xl, 0);
    gemm_bias_kernel<<<gemm_grid, 256, GEMM_SMEM>>>(emb, Wr1,   br1,   xr, 0);
    gemm_bias_kernel<<<gemm_grid, 256, GEMM_SMEM>>>(emb, Wres1, bias1, h,  0);
    edge_logits_kernel<<<edge_grid, 256>>>(ei, xl, xr, att1, ex, denom);
    edge_aggr_kernel  <<<edge_grid, 256>>>(ei, xl, ex, denom, h);

    // ---- layer 2 (ReLU fused into GEMM A-tile load) ----
    cudaMemsetAsync(denom, 0, NN * sizeof(float));
    gemm_bias_kernel<<<gemm_grid, 256, GEMM_SMEM>>>(h, Wl2,   bl2,   xl,  1);
    gemm_bias_kernel<<<gemm_grid, 256, GEMM_SMEM>>>(h, Wr2,   br2,   xr,  1);
    gemm_bias_kernel<<<gemm_grid, 256, GEMM_SMEM>>>(h, Wres2, bias2, out, 1);
    edge_logits_kernel<<<edge_grid, 256>>>(ei, xl, xr, att2, ex, denom);
    edge_aggr_kernel  <<<edge_grid, 256>>>(ei, xl, ex, denom, out);
}

// round 4
// speedup vs baseline: 3.0554x; 3.0554x over previous
#include <cuda_runtime.h>
#include <cuda_bf16.h>
#include <cstdint>

#define NN 100000
#define EE 640000
#define EP 740000            /* EE + NN self loops */
#define CC 128
#define NEG_SLOPE 0.2f
#define SCAN_BLK 1024
#define NBLK ((NN + SCAN_BLK - 1) / SCAN_BLK)   /* 98 */

// ---------------- device scratch ---------------------------------------------
__device__ __align__(16) float g_xl[(size_t)NN * CC];
__device__ __align__(16) float g_xr[(size_t)NN * CC];
__device__ __align__(16) float g_h [(size_t)NN * CC];
__device__ int   g_deg[NN];
__device__ int   g_cur[NN];
__device__ int   g_off[NN];
__device__ int   g_bsum[NBLK];
__device__ int   g_csr[EP];

// ---------------- CSR build ---------------------------------------------------
__global__ void hist_kernel(const int* __restrict__ ei) {
    int e = blockIdx.x * blockDim.x + threadIdx.x;
    if (e >= EP) return;
    int d = (e < EE) ? ei[EE + e] : (e - EE);
    atomicAdd(&g_deg[d], 1);
}

__global__ void scan1_kernel() {
    __shared__ int sh[SCAN_BLK];
    int i = blockIdx.x * SCAN_BLK + threadIdx.x;
    int v = (i < NN) ? g_deg[i] : 0;
    sh[threadIdx.x] = v;
    __syncthreads();
    for (int o = 1; o < SCAN_BLK; o <<= 1) {
        int t = (threadIdx.x >= o) ? sh[threadIdx.x - o] : 0;
        __syncthreads();
        sh[threadIdx.x] += t;
        __syncthreads();
    }
    if (i < NN) g_off[i] = sh[threadIdx.x] - v;           // block-exclusive
    if (threadIdx.x == SCAN_BLK - 1) g_bsum[blockIdx.x] = sh[threadIdx.x];
}

__global__ void scan2_kernel() {                           // 1 block, 128 thr
    __shared__ int sh[128];
    int b = threadIdx.x;
    int v = (b < NBLK) ? g_bsum[b] : 0;
    sh[b] = v;
    __syncthreads();
    for (int o = 1; o < 128; o <<= 1) {
        int t = (b >= o) ? sh[b - o] : 0;
        __syncthreads();
        sh[b] += t;
        __syncthreads();
    }
    if (b < NBLK) g_bsum[b] = sh[b] - v;                   // exclusive
}

__global__ void scan3_kernel() {
    int i = blockIdx.x * blockDim.x + threadIdx.x;
    if (i < NN) g_off[i] += g_bsum[i / SCAN_BLK];
}

__global__ void scatter_kernel(const int* __restrict__ ei) {
    int e = blockIdx.x * blockDim.x + threadIdx.x;
    if (e >= EP) return;
    int s, d;
    if (e < EE) { s = ei[e]; d = ei[EE + e]; }
    else        { s = d = e - EE; }
    int pos = g_off[d] + atomicAdd(&g_cur[d], 1);
    g_csr[pos] = s;
}

// ---------------- fused 3-output GEMM ----------------------------------------
// out_j[n][c] = b_j[c] + sum_k f(x[n][k]) * W_j[c][k],  f = relu if relu_in.
// Tile M=128, full N=128, K in 2 chunks of 64. 256 thr, 8x8 microtile split
// 4+4 in each dim. As row-major, Bs k-major with BS_STRIDE=132: multiple of 4
// keeps every float4 LDS 16B-aligned (129 trapped: misaligned LDS.128), and
// the +4-float row skew shifts banks between k-rows.
#define BS_STRIDE 132
__global__ __launch_bounds__(256, 2) void gemm3_kernel(
    const float* __restrict__ x,
    const float* __restrict__ W0, const float* __restrict__ b0, float* __restrict__ o0,
    const float* __restrict__ W1, const float* __restrict__ b1, float* __restrict__ o1,
    const float* __restrict__ W2, const float* __restrict__ b2, float* __restrict__ o2,
    int relu_in)
{
    extern __shared__ float sm[];
    float* As = sm;                       // [128][128]
    float* Bs = sm + 128 * 128;           // [64][BS_STRIDE]

    const int tid  = threadIdx.x;
    const int row0 = blockIdx.x * 128;
    const int tx   = tid & 15;            // cols tx*4, 64+tx*4
    const int ty   = tid >> 4;            // rows ty*4, 64+ty*4
    const int tx4  = tx * 4;
    const int ty4  = ty * 4;

    // load A tile (plain row-major copy, optionally relu'd)
#pragma unroll
    for (int t = 0; t < 16; t++) {
        int idx = tid + t * 256;          // 4096 float4 total
        int m   = idx >> 5;
        int k4  = (idx & 31) << 2;
        int gr  = row0 + m;
        float4 v = make_float4(0.f, 0.f, 0.f, 0.f);
        if (gr < NN) v = *(const float4*)(x + (size_t)gr * CC + k4);
        if (relu_in) {
            v.x = fmaxf(v.x, 0.f); v.y = fmaxf(v.y, 0.f);
            v.z = fmaxf(v.z, 0.f); v.w = fmaxf(v.w, 0.f);
        }
        *(float4*)(As + m * 128 + k4) = v;
    }

    const float* Ws[3] = {W0, W1, W2};
    const float* bs[3] = {b0, b1, b2};
    float*       os[3] = {o0, o1, o2};

    for (int j = 0; j < 3; j++) {
        const float* W = Ws[j];
        float acc[8][8];
#pragma unroll
        for (int i = 0; i < 8; i++)
#pragma unroll
            for (int q = 0; q < 8; q++) acc[i][q] = 0.f;

        for (int kc = 0; kc < 2; kc++) {
            __syncthreads();              // A visible / previous Bs consumed
            // load Bs[k][c] = W[c][kc*64 + k]
#pragma unroll
            for (int t = 0; t < 8; t++) {
                int idx = tid + t * 256;  // 2048 float4 total
                int c   = idx >> 4;
                int k4  = (idx & 15) << 2;
                float4 w = *(const float4*)(W + c * 128 + kc * 64 + k4);
                Bs[(k4 + 0) * BS_STRIDE + c] = w.x;
                Bs[(k4 + 1) * BS_STRIDE + c] = w.y;
                Bs[(k4 + 2) * BS_STRIDE + c] = w.z;
                Bs[(k4 + 3) * BS_STRIDE + c] = w.w;
            }
            __syncthreads();

#pragma unroll 8
            for (int kk = 0; kk < 64; kk++) {
                int k = kc * 64 + kk;
                float av[8], bv[8];
#pragma unroll
                for (int i = 0; i < 4; i++) {
                    av[i]     = As[(ty4 + i) * 128 + k];
                    av[i + 4] = As[(64 + ty4 + i) * 128 + k];
                }
                float4 bA = *(const float4*)(Bs + kk * BS_STRIDE + tx4);
                float4 bB = *(const float4*)(Bs + kk * BS_STRIDE + 64 + tx4);
                bv[0] = bA.x; bv[1] = bA.y; bv[2] = bA.z; bv[3] = bA.w;
                bv[4] = bB.x; bv[5] = bB.y; bv[6] = bB.z; bv[7] = bB.w;
#pragma unroll
                for (int i = 0; i < 8; i++)
#pragma unroll
                    for (int q = 0; q < 8; q++)
                        acc[i][q] = fmaf(av[i], bv[q], acc[i][q]);
            }
        }

        // epilogue
        float4 bi0 = *(const float4*)(bs[j] + tx4);
        float4 bi1 = *(const float4*)(bs[j] + 64 + tx4);
        float* o = os[j];
#pragma unroll
        for (int i = 0; i < 8; i++) {
            int gr = row0 + ((i < 4) ? (ty4 + i) : (64 + ty4 + i - 4));
            if (gr >= NN) continue;
            float4 v0 = make_float4(acc[i][0] + bi0.x, acc[i][1] + bi0.y,
                                    acc[i][2] + bi0.z, acc[i][3] + bi0.w);
            float4 v1 = make_float4(acc[i][4] + bi1.x, acc[i][5] + bi1.y,
                                    acc[i][6] + bi1.z, acc[i][7] + bi1.w);
            *(float4*)(o + (size_t)gr * CC + tx4)      = v0;
            *(float4*)(o + (size_t)gr * CC + 64 + tx4) = v1;
        }
    }
}

// ---------------- fused attention + aggregation (warp per dst, no atomics) ---
// out[d] = (sum_e exp(att . leaky(xl[s_e] + xr[d])) * xl[s_e]) / denom + res[d]
// Softmax max-shift elided (|logit| << 88, exp cannot overflow).
__global__ __launch_bounds__(256) void aggr_kernel(
    const float* __restrict__ xl, const float* __restrict__ xr,
    const float* __restrict__ att, float* __restrict__ res_out)
{
    int gw   = (int)((blockIdx.x * 256u + threadIdx.x) >> 5);
    int lane = threadIdx.x & 31;
    if (gw >= NN) return;
    const int d = gw;

    float4 t = *(const float4*)(att + lane * 4);
    float4 r = *(const float4*)(xr + (size_t)d * CC + lane * 4);

    const int start = g_off[d];
    const int deg   = g_deg[d];          // >= 1 (self loop)

    float denom = 0.f;
    float4 acc = make_float4(0.f, 0.f, 0.f, 0.f);

    int s = g_csr[start];
    float4 a = *(const float4*)(xl + (size_t)s * CC + lane * 4);

    for (int jj = 0; jj < deg; jj++) {
        float4 cur = a;
        if (jj + 1 < deg) {              // prefetch next row (MLP=2)
            int s2 = g_csr[start + jj + 1];
            a = *(const float4*)(xl + (size_t)s2 * CC + lane * 4);
        }
        float4 m;
        m.x = cur.x + r.x; m.x = m.x > 0.f ? m.x : NEG_SLOPE * m.x;
        m.y = cur.y + r.y; m.y = m.y > 0.f ? m.y : NEG_SLOPE * m.y;
        m.z = cur.z + r.z; m.z = m.z > 0.f ? m.z : NEG_SLOPE * m.z;
        m.w = cur.w + r.w; m.w = m.w > 0.f ? m.w : NEG_SLOPE * m.w;

        float p = m.x * t.x;
        p = fmaf(m.y, t.y, p);
        p = fmaf(m.z, t.z, p);
        p = fmaf(m.w, t.w, p);
#pragma unroll
        for (int off = 16; off > 0; off >>= 1)
            p += __shfl_xor_sync(0xffffffffu, p, off);

        float ev = expf(p);
        denom += ev;
        acc.x = fmaf(ev, cur.x, acc.x);
        acc.y = fmaf(ev, cur.y, acc.y);
        acc.z = fmaf(ev, cur.z, acc.z);
        acc.w = fmaf(ev, cur.w, acc.w);
    }

    float inv = 1.f / denom;
    float* op = res_out + (size_t)d * CC + lane * 4;
    float4 rr = *(const float4*)op;
    float4 o = make_float4(fmaf(acc.x, inv, rr.x), fmaf(acc.y, inv, rr.y),
                           fmaf(acc.z, inv, rr.z), fmaf(acc.w, inv, rr.w));
    *(float4*)op = o;
}

// ---------------- launch ------------------------------------------------------
extern "C" void kernel_launch(void* const* d_in, const int* in_sizes, int n_in,
                              void* d_out, int out_size)
{
    const int*   ei    = (const int*)  d_in[0];
    const float* emb   = (const float*)d_in[1];
    const float* Wl1   = (const float*)d_in[2];
    const float* bl1   = (const float*)d_in[3];
    const float* Wr1   = (const float*)d_in[4];
    const float* br1   = (const float*)d_in[5];
    const float* att1  = (const float*)d_in[6];
    const float* Wres1 = (const float*)d_in[7];
    const float* bias1 = (const float*)d_in[8];
    const float* Wl2   = (const float*)d_in[9];
    const float* bl2   = (const float*)d_in[10];
    const float* Wr2   = (const float*)d_in[11];
    const float* br2   = (const float*)d_in[12];
    const float* att2  = (const float*)d_in[13];
    const float* Wres2 = (const float*)d_in[14];
    const float* bias2 = (const float*)d_in[15];
    float* out = (float*)d_out;

    float *xl, *xr, *h;
    int *deg, *cur;
    cudaGetSymbolAddress((void**)&xl,  g_xl);
    cudaGetSymbolAddress((void**)&xr,  g_xr);
    cudaGetSymbolAddress((void**)&h,   g_h);
    cudaGetSymbolAddress((void**)&deg, g_deg);
    cudaGetSymbolAddress((void**)&cur, g_cur);

    const int GEMM_SMEM = (128 * 128 + 64 * BS_STRIDE) * sizeof(float); // ~99.3 KB
    cudaFuncSetAttribute(gemm3_kernel,
                         cudaFuncAttributeMaxDynamicSharedMemorySize, GEMM_SMEM);

    const int edge_grid = (EP + 255) / 256;        // 2891
    const int gemm_grid = (NN + 127) / 128;        // 782
    const int aggr_grid = (NN * 32 + 255) / 256;   // 12500

    // ---- CSR build (shared by both layers) ----
    cudaMemsetAsync(deg, 0, NN * sizeof(int));
    cudaMemsetAsync(cur, 0, NN * sizeof(int));
    hist_kernel<<<edge_grid, 256>>>(ei);
    scan1_kernel<<<NBLK, SCAN_BLK>>>();
    scan2_kernel<<<1, 128>>>();
    scan3_kernel<<<(NN + 255) / 256, 256>>>();
    scatter_kernel<<<edge_grid, 256>>>(ei);

    // ---- layer 1 ----
    gemm3_kernel<<<gemm_grid, 256, GEMM_SMEM>>>(
        emb, Wl1, bl1, xl, Wr1, br1, xr, Wres1, bias1, h, 0);
    aggr_kernel<<<aggr_grid, 256>>>(xl, xr, att1, h);

    // ---- layer 2 (ReLU fused into GEMM A-tile load) ----
    gemm3_kernel<<<gemm_grid, 256, GEMM_SMEM>>>(
        h, Wl2, bl2, xl, Wr2, br2, xr, Wres2, bias2, out, 1);
    aggr_kernel<<<aggr_grid, 256>>>(xl, xr, att2, out);
}

// round 7
// speedup vs baseline: 4.0242x; 1.3171x over previous
#include <cuda_runtime.h>
#include <cuda_bf16.h>
#include <cstdint>

#define NN 100000
#define EE 640000
#define EP 740000            /* EE + NN self loops */
#define CC 128
#define NEG_SLOPE 0.2f
#define SCAN_BLK 1024
#define NBLK ((NN + SCAN_BLK - 1) / SCAN_BLK)   /* 98 */

// ---------------- device scratch ---------------------------------------------
__device__ __align__(16) float g_xl[(size_t)NN * CC];
__device__ __align__(16) float g_xr[(size_t)NN * CC];
__device__ __align__(16) float g_h [(size_t)NN * CC];
__device__ int   g_deg[NN];
__device__ int   g_cur[NN];
__device__ int   g_off[NN];
__device__ int   g_bsum[NBLK];
__device__ int   g_csr[EP];

// ---------------- CSR build ---------------------------------------------------
__global__ void hist_kernel(const int* __restrict__ ei) {
    int e = blockIdx.x * blockDim.x + threadIdx.x;
    if (e >= EP) return;
    int d = (e < EE) ? ei[EE + e] : (e - EE);
    atomicAdd(&g_deg[d], 1);
}

__global__ void scan1_kernel() {
    __shared__ int sh[SCAN_BLK];
    int i = blockIdx.x * SCAN_BLK + threadIdx.x;
    int v = (i < NN) ? g_deg[i] : 0;
    sh[threadIdx.x] = v;
    __syncthreads();
    for (int o = 1; o < SCAN_BLK; o <<= 1) {
        int t = (threadIdx.x >= o) ? sh[threadIdx.x - o] : 0;
        __syncthreads();
        sh[threadIdx.x] += t;
        __syncthreads();
    }
    if (i < NN) g_off[i] = sh[threadIdx.x] - v;
    if (threadIdx.x == SCAN_BLK - 1) g_bsum[blockIdx.x] = sh[threadIdx.x];
}

__global__ void scan2_kernel() {
    __shared__ int sh[128];
    int b = threadIdx.x;
    int v = (b < NBLK) ? g_bsum[b] : 0;
    sh[b] = v;
    __syncthreads();
    for (int o = 1; o < 128; o <<= 1) {
        int t = (b >= o) ? sh[b - o] : 0;
        __syncthreads();
        sh[b] += t;
        __syncthreads();
    }
    if (b < NBLK) g_bsum[b] = sh[b] - v;
}

__global__ void scan3_kernel() {
    int i = blockIdx.x * blockDim.x + threadIdx.x;
    if (i < NN) g_off[i] += g_bsum[i / SCAN_BLK];
}

__global__ void scatter_kernel(const int* __restrict__ ei) {
    int e = blockIdx.x * blockDim.x + threadIdx.x;
    if (e >= EP) return;
    int s, d;
    if (e < EE) { s = ei[e]; d = ei[EE + e]; }
    else        { s = d = e - EE; }
    int pos = g_off[d] + atomicAdd(&g_cur[d], 1);
    g_csr[pos] = s;
}

// ================= HMMA (mma.sync) 3-output GEMM ==============================
// out_j[n][c] = b_j[c] + sum_k f(x[n][k]) * W_j[c][k]
// fp32 operands split hi+lo (bf16); D = Ah*Bh + Ah*Bl + Al*Bh (lo*lo dropped,
// ~2^-18 rel). m16n8k16 row.col fragments via plain LDS (stride 136 bf16 ->
// banks n*4+tg, conflict-free). 8 warps = 2(m)x4(n) warp tiles of 64x32.
#define AS_STRIDE 136                    /* bf16 units, even & bank-clean */
#define TILE_B (128 * AS_STRIDE * 2)     /* 34816 bytes per tile */
#define SM_AHI 0
#define SM_ALO (TILE_B)
#define SM_BHI (2 * TILE_B)
#define SM_BLO (3 * TILE_B)
#define SM_TOTAL (4 * TILE_B)            /* 139264 */

__device__ __forceinline__ void mma16816(float* c, const uint32_t* a,
                                         const uint32_t* b) {
    asm volatile(
        "mma.sync.aligned.m16n8k16.row.col.f32.bf16.bf16.f32 "
        "{%0,%1,%2,%3}, {%4,%5,%6,%7}, {%8,%9}, {%0,%1,%2,%3};"
        : "+f"(c[0]), "+f"(c[1]), "+f"(c[2]), "+f"(c[3])
        : "r"(a[0]), "r"(a[1]), "r"(a[2]), "r"(a[3]), "r"(b[0]), "r"(b[1]));
}

__device__ __forceinline__ void cvt_pair(char* hi, char* lo, int row, int k,
                                         float a, float b) {
    __nv_bfloat16 h0 = __float2bfloat16(a), h1 = __float2bfloat16(b);
    __nv_bfloat16 l0 = __float2bfloat16(a - __bfloat162float(h0));
    __nv_bfloat16 l1 = __float2bfloat16(b - __bfloat162float(h1));
    uint32_t hw = (uint32_t)__bfloat16_as_ushort(h0)
                | ((uint32_t)__bfloat16_as_ushort(h1) << 16);
    uint32_t lw = (uint32_t)__bfloat16_as_ushort(l0)
                | ((uint32_t)__bfloat16_as_ushort(l1) << 16);
    uint32_t off = (uint32_t)(row * AS_STRIDE + k) * 2;
    *(uint32_t*)(hi + off) = hw;
    *(uint32_t*)(lo + off) = lw;
}

__device__ __forceinline__ void load_tile_split(const float* src, int nrows,
                                                int relu, char* hi, char* lo,
                                                int tid) {
#pragma unroll
    for (int t = 0; t < 16; t++) {
        int idx = tid + t * 256;         // 4096 float4 total
        int row = idx >> 5;
        int k4  = (idx & 31) << 2;
        float4 v = make_float4(0.f, 0.f, 0.f, 0.f);
        if (row < nrows) v = *(const float4*)(src + (size_t)row * CC + k4);
        if (relu) {
            v.x = fmaxf(v.x, 0.f); v.y = fmaxf(v.y, 0.f);
            v.z = fmaxf(v.z, 0.f); v.w = fmaxf(v.w, 0.f);
        }
        cvt_pair(hi, lo, row, k4,     v.x, v.y);
        cvt_pair(hi, lo, row, k4 + 2, v.z, v.w);
    }
}

__global__ __launch_bounds__(256, 1) void gemm3_tc_kernel(
    const float* __restrict__ x,
    const float* __restrict__ W0, const float* __restrict__ b0, float* __restrict__ o0,
    const float* __restrict__ W1, const float* __restrict__ b1, float* __restrict__ o1,
    const float* __restrict__ W2, const float* __restrict__ b2, float* __restrict__ o2,
    int relu_in)
{
    extern __shared__ char sm[];
    const int tid  = threadIdx.x;
    const int wid  = tid >> 5;
    const int lane = tid & 31;
    const int g    = lane >> 2;          // 0..7
    const int tg   = lane & 3;           // 0..3
    const int row0 = blockIdx.x * 128;
    const int nrows = (NN - row0 < 128) ? (NN - row0) : 128;
    const int wm0 = (wid >> 2) * 64;     // warp tile m origin (0 / 64)
    const int wn0 = (wid & 3) * 32;      // warp tile n origin (0/32/64/96)

    // A tile -> bf16 hi/lo (once)
    load_tile_split(x + (size_t)row0 * CC, nrows, relu_in,
                    sm + SM_AHI, sm + SM_ALO, tid);

    const float* Ws[3] = {W0, W1, W2};
    const float* bs[3] = {b0, b1, b2};
    float*       os[3] = {o0, o1, o2};

    const __nv_bfloat16* Ah = (const __nv_bfloat16*)(sm + SM_AHI);
    const __nv_bfloat16* Al = (const __nv_bfloat16*)(sm + SM_ALO);
    const __nv_bfloat16* Bh = (const __nv_bfloat16*)(sm + SM_BHI);
    const __nv_bfloat16* Bl = (const __nv_bfloat16*)(sm + SM_BLO);

    for (int j = 0; j < 3; j++) {
        __syncthreads();                 // previous Bs fully consumed
        load_tile_split(Ws[j], 128, 0, sm + SM_BHI, sm + SM_BLO, tid);
        __syncthreads();

        float acc[4][4][4];
#pragma unroll
        for (int ma = 0; ma < 4; ma++)
#pragma unroll
            for (int na = 0; na < 4; na++)
#pragma unroll
                for (int q = 0; q < 4; q++) acc[ma][na][q] = 0.f;

#pragma unroll
        for (int ks = 0; ks < 8; ks++) {
            const int kb = ks * 16 + tg * 2;     // bf16 col of pair
            uint32_t bh[4][2], bl[4][2], af[4][4];
#pragma unroll
            for (int na = 0; na < 4; na++) {
                int n = wn0 + na * 8 + g;
                bh[na][0] = *(const uint32_t*)(Bh + n * AS_STRIDE + kb);
                bh[na][1] = *(const uint32_t*)(Bh + n * AS_STRIDE + kb + 8);
                bl[na][0] = *(const uint32_t*)(Bl + n * AS_STRIDE + kb);
                bl[na][1] = *(const uint32_t*)(Bl + n * AS_STRIDE + kb + 8);
            }
            // A_hi fragments
#pragma unroll
            for (int ma = 0; ma < 4; ma++) {
                int m = wm0 + ma * 16 + g;
                af[ma][0] = *(const uint32_t*)(Ah + m * AS_STRIDE + kb);
                af[ma][1] = *(const uint32_t*)(Ah + (m + 8) * AS_STRIDE + kb);
                af[ma][2] = *(const uint32_t*)(Ah + m * AS_STRIDE + kb + 8);
                af[ma][3] = *(const uint32_t*)(Ah + (m + 8) * AS_STRIDE + kb + 8);
            }
#pragma unroll
            for (int ma = 0; ma < 4; ma++)
#pragma unroll
                for (int na = 0; na < 4; na++)
                    mma16816(acc[ma][na], af[ma], bh[na]);
#pragma unroll
            for (int ma = 0; ma < 4; ma++)
#pragma unroll
                for (int na = 0; na < 4; na++)
                    mma16816(acc[ma][na], af[ma], bl[na]);
            // A_lo fragments (reuse af regs)
#pragma unroll
            for (int ma = 0; ma < 4; ma++) {
                int m = wm0 + ma * 16 + g;
                af[ma][0] = *(const uint32_t*)(Al + m * AS_STRIDE + kb);
                af[ma][1] = *(const uint32_t*)(Al + (m + 8) * AS_STRIDE + kb);
                af[ma][2] = *(const uint32_t*)(Al + m * AS_STRIDE + kb + 8);
                af[ma][3] = *(const uint32_t*)(Al + (m + 8) * AS_STRIDE + kb + 8);
            }
#pragma unroll
            for (int ma = 0; ma < 4; ma++)
#pragma unroll
                for (int na = 0; na < 4; na++)
                    mma16816(acc[ma][na], af[ma], bh[na]);
        }

        // epilogue: bias + direct gmem stores (float2 per atom-half)
        const float* bias = bs[j];
        float* o = os[j];
#pragma unroll
        for (int na = 0; na < 4; na++) {
            int col = wn0 + na * 8 + tg * 2;
            float2 bb = *(const float2*)(bias + col);
#pragma unroll
            for (int ma = 0; ma < 4; ma++) {
                int ra = row0 + wm0 + ma * 16 + g;
                if (ra < NN) {
                    float2 v = make_float2(acc[ma][na][0] + bb.x,
                                           acc[ma][na][1] + bb.y);
                    *(float2*)(o + (size_t)ra * CC + col) = v;
                }
                int rb = ra + 8;
                if (rb < NN) {
                    float2 v = make_float2(acc[ma][na][2] + bb.x,
                                           acc[ma][na][3] + bb.y);
                    *(float2*)(o + (size_t)rb * CC + col) = v;
                }
            }
        }
    }
}

// ---------------- fused attention + aggregation (warp per dst, no atomics) ---
__global__ __launch_bounds__(256) void aggr_kernel(
    const float* __restrict__ xl, const float* __restrict__ xr,
    const float* __restrict__ att, float* __restrict__ res_out)
{
    int gw   = (int)((blockIdx.x * 256u + threadIdx.x) >> 5);
    int lane = threadIdx.x & 31;
    if (gw >= NN) return;
    const int d = gw;

    float4 t = *(const float4*)(att + lane * 4);
    float4 r = *(const float4*)(xr + (size_t)d * CC + lane * 4);

    const int start = g_off[d];
    const int deg   = g_deg[d];          // >= 1 (self loop)

    float denom = 0.f;
    float4 acc = make_float4(0.f, 0.f, 0.f, 0.f);

    int s = g_csr[start];
    float4 a = *(const float4*)(xl + (size_t)s * CC + lane * 4);

    for (int jj = 0; jj < deg; jj++) {
        float4 cur = a;
        if (jj + 1 < deg) {              // prefetch next row (MLP=2)
            int s2 = g_csr[start + jj + 1];
            a = *(const float4*)(xl + (size_t)s2 * CC + lane * 4);
        }
        float4 m;
        m.x = cur.x + r.x; m.x = m.x > 0.f ? m.x : NEG_SLOPE * m.x;
        m.y = cur.y + r.y; m.y = m.y > 0.f ? m.y : NEG_SLOPE * m.y;
        m.z = cur.z + r.z; m.z = m.z > 0.f ? m.z : NEG_SLOPE * m.z;
        m.w = cur.w + r.w; m.w = m.w > 0.f ? m.w : NEG_SLOPE * m.w;

        float p = m.x * t.x;
        p = fmaf(m.y, t.y, p);
        p = fmaf(m.z, t.z, p);
        p = fmaf(m.w, t.w, p);
#pragma unroll
        for (int off = 16; off > 0; off >>= 1)
            p += __shfl_xor_sync(0xffffffffu, p, off);

        float ev = expf(p);
        denom += ev;
        acc.x = fmaf(ev, cur.x, acc.x);
        acc.y = fmaf(ev, cur.y, acc.y);
        acc.z = fmaf(ev, cur.z, acc.z);
        acc.w = fmaf(ev, cur.w, acc.w);
    }

    float inv = 1.f / denom;
    float* op = res_out + (size_t)d * CC + lane * 4;
    float4 rr = *(const float4*)op;
    float4 o = make_float4(fmaf(acc.x, inv, rr.x), fmaf(acc.y, inv, rr.y),
                           fmaf(acc.z, inv, rr.z), fmaf(acc.w, inv, rr.w));
    *(float4*)op = o;
}

// ---------------- launch ------------------------------------------------------
extern "C" void kernel_launch(void* const* d_in, const int* in_sizes, int n_in,
                              void* d_out, int out_size)
{
    const int*   ei    = (const int*)  d_in[0];
    const float* emb   = (const float*)d_in[1];
    const float* Wl1   = (const float*)d_in[2];
    const float* bl1   = (const float*)d_in[3];
    const float* Wr1   = (const float*)d_in[4];
    const float* br1   = (const float*)d_in[5];
    const float* att1  = (const float*)d_in[6];
    const float* Wres1 = (const float*)d_in[7];
    const float* bias1 = (const float*)d_in[8];
    const float* Wl2   = (const float*)d_in[9];
    const float* bl2   = (const float*)d_in[10];
    const float* Wr2   = (const float*)d_in[11];
    const float* br2   = (const float*)d_in[12];
    const float* att2  = (const float*)d_in[13];
    const float* Wres2 = (const float*)d_in[14];
    const float* bias2 = (const float*)d_in[15];
    float* out = (float*)d_out;

    float *xl, *xr, *h;
    int *deg, *cur;
    cudaGetSymbolAddress((void**)&xl,  g_xl);
    cudaGetSymbolAddress((void**)&xr,  g_xr);
    cudaGetSymbolAddress((void**)&h,   g_h);
    cudaGetSymbolAddress((void**)&deg, g_deg);
    cudaGetSymbolAddress((void**)&cur, g_cur);

    cudaFuncSetAttribute(gemm3_tc_kernel,
                         cudaFuncAttributeMaxDynamicSharedMemorySize, SM_TOTAL);

    const int edge_grid = (EP + 255) / 256;        // 2891
    const int gemm_grid = (NN + 127) / 128;        // 782
    const int aggr_grid = (NN * 32 + 255) / 256;   // 12500

    // ---- CSR build (shared by both layers) ----
    cudaMemsetAsync(deg, 0, NN * sizeof(int));
    cudaMemsetAsync(cur, 0, NN * sizeof(int));
    hist_kernel<<<edge_grid, 256>>>(ei);
    scan1_kernel<<<NBLK, SCAN_BLK>>>();
    scan2_kernel<<<1, 128>>>();
    scan3_kernel<<<(NN + 255) / 256, 256>>>();
    scatter_kernel<<<edge_grid, 256>>>(ei);

    // ---- layer 1 ----
    gemm3_tc_kernel<<<gemm_grid, 256, SM_TOTAL>>>(
        emb, Wl1, bl1, xl, Wr1, br1, xr, Wres1, bias1, h, 0);
    aggr_kernel<<<aggr_grid, 256>>>(xl, xr, att1, h);

    // ---- layer 2 (ReLU fused into GEMM operand conversion) ----
    gemm3_tc_kernel<<<gemm_grid, 256, SM_TOTAL>>>(
        h, Wl2, bl2, xl, Wr2, br2, xr, Wres2, bias2, out, 1);
    aggr_kernel<<<aggr_grid, 256>>>(xl, xr, att2, out);
}

// round 8
// speedup vs baseline: 5.3512x; 1.3297x over previous
#include <cuda_runtime.h>
#include <cuda_bf16.h>
#include <cstdint>

#define NN 100000
#define EE 640000
#define EP 740000            /* EE + NN self loops */
#define CC 128
#define NEG_SLOPE 0.2f
#define SCAN_BLK 1024
#define NBLK ((NN + SCAN_BLK - 1) / SCAN_BLK)   /* 98 */

// ---------------- device scratch ---------------------------------------------
__device__ __align__(16) float g_xl[(size_t)NN * CC];
__device__ __align__(16) float g_xr[(size_t)NN * CC];
__device__ __align__(16) float g_h [(size_t)NN * CC];
__device__ __align__(16) __nv_bfloat16 g_Wh[6 * CC * CC];  // weights hi (bf16)
__device__ __align__(16) __nv_bfloat16 g_Wl[6 * CC * CC];  // weights lo (bf16)
__device__ int   g_deg[NN];
__device__ int   g_cur[NN];
__device__ int   g_off[NN];
__device__ int   g_bsum[NBLK];
__device__ int   g_csr[EP];

// ---------------- weight pre-split (fp32 -> bf16 hi/lo) -----------------------
__global__ void wsplit_kernel(const float* __restrict__ W0, const float* __restrict__ W1,
                              const float* __restrict__ W2, const float* __restrict__ W3,
                              const float* __restrict__ W4, const float* __restrict__ W5)
{
    const float* Ws[6] = {W0, W1, W2, W3, W4, W5};
    int i = blockIdx.x * blockDim.x + threadIdx.x;
    if (i >= 6 * CC * CC) return;
    float v = Ws[i >> 14][i & 16383];
    __nv_bfloat16 h = __float2bfloat16(v);
    __nv_bfloat16 l = __float2bfloat16(v - __bfloat162float(h));
    g_Wh[i] = h;
    g_Wl[i] = l;
}

// ---------------- CSR build ---------------------------------------------------
__global__ void hist_kernel(const int* __restrict__ ei) {
    int e = blockIdx.x * blockDim.x + threadIdx.x;
    if (e >= EP) return;
    int d = (e < EE) ? ei[EE + e] : (e - EE);
    atomicAdd(&g_deg[d], 1);
}

__global__ void scan1_kernel() {
    __shared__ int sh[SCAN_BLK];
    int i = blockIdx.x * SCAN_BLK + threadIdx.x;
    int v = (i < NN) ? g_deg[i] : 0;
    sh[threadIdx.x] = v;
    __syncthreads();
    for (int o = 1; o < SCAN_BLK; o <<= 1) {
        int t = (threadIdx.x >= o) ? sh[threadIdx.x - o] : 0;
        __syncthreads();
        sh[threadIdx.x] += t;
        __syncthreads();
    }
    if (i < NN) g_off[i] = sh[threadIdx.x] - v;
    if (threadIdx.x == SCAN_BLK - 1) g_bsum[blockIdx.x] = sh[threadIdx.x];
}

__global__ void scan2_kernel() {
    __shared__ int sh[128];
    int b = threadIdx.x;
    int v = (b < NBLK) ? g_bsum[b] : 0;
    sh[b] = v;
    __syncthreads();
    for (int o = 1; o < 128; o <<= 1) {
        int t = (b >= o) ? sh[b - o] : 0;
        __syncthreads();
        sh[b] += t;
        __syncthreads();
    }
    if (b < NBLK) g_bsum[b] = sh[b] - v;
}

__global__ void scan3_kernel() {
    int i = blockIdx.x * blockDim.x + threadIdx.x;
    if (i < NN) g_off[i] += g_bsum[i / SCAN_BLK];
}

__global__ void scatter_kernel(const int* __restrict__ ei) {
    int e = blockIdx.x * blockDim.x + threadIdx.x;
    if (e >= EP) return;
    int s, d;
    if (e < EE) { s = ei[e]; d = ei[EE + e]; }
    else        { s = d = e - EE; }
    int pos = g_off[d] + atomicAdd(&g_cur[d], 1);
    g_csr[pos] = s;
}

// ================= HMMA (mma.sync) 3-output GEMM ==============================
// out_j[n][c] = b_j[c] + sum_k f(x[n][k]) * W_j[c][k]
// fp32 split hi+lo bf16; D = Ah*Bh + Ah*Bl + Al*Bh (lo*lo dropped, ~2^-18 rel).
// m16n8k16 row.col fragments via plain LDS (stride 136 bf16 -> banks 4g+tg,
// conflict-free). 8 warps = 2(m)x4(n) warp tiles of 64x32. W pre-split in gmem.
#define AS_STRIDE 136                    /* bf16 units, even & bank-clean */
#define TILE_B (128 * AS_STRIDE * 2)     /* 34816 bytes per tile */
#define SM_AHI 0
#define SM_ALO (TILE_B)
#define SM_BHI (2 * TILE_B)
#define SM_BLO (3 * TILE_B)
#define SM_TOTAL (4 * TILE_B)            /* 139264 */

__device__ __forceinline__ void mma16816(float* c, const uint32_t* a,
                                         const uint32_t* b) {
    asm volatile(
        "mma.sync.aligned.m16n8k16.row.col.f32.bf16.bf16.f32 "
        "{%0,%1,%2,%3}, {%4,%5,%6,%7}, {%8,%9}, {%0,%1,%2,%3};"
        : "+f"(c[0]), "+f"(c[1]), "+f"(c[2]), "+f"(c[3])
        : "r"(a[0]), "r"(a[1]), "r"(a[2]), "r"(a[3]), "r"(b[0]), "r"(b[1]));
}

__device__ __forceinline__ void cvt_pair(char* hi, char* lo, int row, int k,
                                         float a, float b) {
    __nv_bfloat16 h0 = __float2bfloat16(a), h1 = __float2bfloat16(b);
    __nv_bfloat16 l0 = __float2bfloat16(a - __bfloat162float(h0));
    __nv_bfloat16 l1 = __float2bfloat16(b - __bfloat162float(h1));
    uint32_t hw = (uint32_t)__bfloat16_as_ushort(h0)
                | ((uint32_t)__bfloat16_as_ushort(h1) << 16);
    uint32_t lw = (uint32_t)__bfloat16_as_ushort(l0)
                | ((uint32_t)__bfloat16_as_ushort(l1) << 16);
    uint32_t off = (uint32_t)(row * AS_STRIDE + k) * 2;
    *(uint32_t*)(hi + off) = hw;
    *(uint32_t*)(lo + off) = lw;
}

__device__ __forceinline__ void load_a_split(const float* src, int nrows,
                                             int relu, char* hi, char* lo,
                                             int tid) {
#pragma unroll
    for (int t = 0; t < 16; t++) {
        int idx = tid + t * 256;         // 4096 float4 total
        int row = idx >> 5;
        int k4  = (idx & 31) << 2;
        float4 v = make_float4(0.f, 0.f, 0.f, 0.f);
        if (row < nrows) v = *(const float4*)(src + (size_t)row * CC + k4);
        if (relu) {
            v.x = fmaxf(v.x, 0.f); v.y = fmaxf(v.y, 0.f);
            v.z = fmaxf(v.z, 0.f); v.w = fmaxf(v.w, 0.f);
        }
        cvt_pair(hi, lo, row, k4,     v.x, v.y);
        cvt_pair(hi, lo, row, k4 + 2, v.z, v.w);
    }
}

// copy pre-split bf16 W tile [128][128] row-major -> smem stride AS_STRIDE
__device__ __forceinline__ void copy_w_tile(const __nv_bfloat16* src, char* dst,
                                            int tid) {
#pragma unroll
    for (int t = 0; t < 8; t++) {
        int idx = tid + t * 256;         // 2048 uint4 (8 bf16 each)
        int row = idx >> 4;
        int k8  = (idx & 15) << 3;
        uint4 v = *(const uint4*)(src + row * CC + k8);
        *(uint4*)(dst + (uint32_t)(row * AS_STRIDE + k8) * 2) = v;
    }
}

__global__ __launch_bounds__(256, 1) void gemm3_tc_kernel(
    const float* __restrict__ x,
    const __nv_bfloat16* __restrict__ Wh, const __nv_bfloat16* __restrict__ Wl,
    int mat0,
    const float* __restrict__ b0, float* __restrict__ o0,
    const float* __restrict__ b1, float* __restrict__ o1,
    const float* __restrict__ b2, float* __restrict__ o2,
    int relu_in)
{
    extern __shared__ char sm[];
    const int tid  = threadIdx.x;
    const int wid  = tid >> 5;
    const int lane = tid & 31;
    const int g    = lane >> 2;          // 0..7
    const int tg   = lane & 3;           // 0..3
    const int row0 = blockIdx.x * 128;
    const int nrows = (NN - row0 < 128) ? (NN - row0) : 128;
    const int wm0 = (wid >> 2) * 64;     // warp tile m origin (0 / 64)
    const int wn0 = (wid & 3) * 32;      // warp tile n origin (0/32/64/96)

    // A tile -> bf16 hi/lo (once)
    load_a_split(x + (size_t)row0 * CC, nrows, relu_in,
                 sm + SM_AHI, sm + SM_ALO, tid);

    const float* bs[3] = {b0, b1, b2};
    float*       os[3] = {o0, o1, o2};

    const __nv_bfloat16* Ah = (const __nv_bfloat16*)(sm + SM_AHI);
    const __nv_bfloat16* Al = (const __nv_bfloat16*)(sm + SM_ALO);
    const __nv_bfloat16* Bh = (const __nv_bfloat16*)(sm + SM_BHI);
    const __nv_bfloat16* Bl = (const __nv_bfloat16*)(sm + SM_BLO);

    for (int j = 0; j < 3; j++) {
        __syncthreads();                 // previous Bs fully consumed
        copy_w_tile(Wh + (size_t)(mat0 + j) * CC * CC, sm + SM_BHI, tid);
        copy_w_tile(Wl + (size_t)(mat0 + j) * CC * CC, sm + SM_BLO, tid);
        __syncthreads();

        float acc[4][4][4];
#pragma unroll
        for (int ma = 0; ma < 4; ma++)
#pragma unroll
            for (int na = 0; na < 4; na++)
#pragma unroll
                for (int q = 0; q < 4; q++) acc[ma][na][q] = 0.f;

#pragma unroll
        for (int ks = 0; ks < 8; ks++) {
            const int kb = ks * 16 + tg * 2;     // bf16 col of pair
            uint32_t bh[4][2], bl[4][2], af[4][4];
#pragma unroll
            for (int na = 0; na < 4; na++) {
                int n = wn0 + na * 8 + g;
                bh[na][0] = *(const uint32_t*)(Bh + n * AS_STRIDE + kb);
                bh[na][1] = *(const uint32_t*)(Bh + n * AS_STRIDE + kb + 8);
                bl[na][0] = *(const uint32_t*)(Bl + n * AS_STRIDE + kb);
                bl[na][1] = *(const uint32_t*)(Bl + n * AS_STRIDE + kb + 8);
            }
            // A_hi fragments
#pragma unroll
            for (int ma = 0; ma < 4; ma++) {
                int m = wm0 + ma * 16 + g;
                af[ma][0] = *(const uint32_t*)(Ah + m * AS_STRIDE + kb);
                af[ma][1] = *(const uint32_t*)(Ah + (m + 8) * AS_STRIDE + kb);
                af[ma][2] = *(const uint32_t*)(Ah + m * AS_STRIDE + kb + 8);
                af[ma][3] = *(const uint32_t*)(Ah + (m + 8) * AS_STRIDE + kb + 8);
            }
#pragma unroll
            for (int ma = 0; ma < 4; ma++)
#pragma unroll
                for (int na = 0; na < 4; na++)
                    mma16816(acc[ma][na], af[ma], bh[na]);
#pragma unroll
            for (int ma = 0; ma < 4; ma++)
#pragma unroll
                for (int na = 0; na < 4; na++)
                    mma16816(acc[ma][na], af[ma], bl[na]);
            // A_lo fragments (reuse af regs)
#pragma unroll
            for (int ma = 0; ma < 4; ma++) {
                int m = wm0 + ma * 16 + g;
                af[ma][0] = *(const uint32_t*)(Al + m * AS_STRIDE + kb);
                af[ma][1] = *(const uint32_t*)(Al + (m + 8) * AS_STRIDE + kb);
                af[ma][2] = *(const uint32_t*)(Al + m * AS_STRIDE + kb + 8);
                af[ma][3] = *(const uint32_t*)(Al + (m + 8) * AS_STRIDE + kb + 8);
            }
#pragma unroll
            for (int ma = 0; ma < 4; ma++)
#pragma unroll
                for (int na = 0; na < 4; na++)
                    mma16816(acc[ma][na], af[ma], bh[na]);
        }

        // epilogue: bias + direct gmem stores (float2 per atom-half)
        const float* bias = bs[j];
        float* o = os[j];
#pragma unroll
        for (int na = 0; na < 4; na++) {
            int col = wn0 + na * 8 + tg * 2;
            float2 bb = *(const float2*)(bias + col);
#pragma unroll
            for (int ma = 0; ma < 4; ma++) {
                int ra = row0 + wm0 + ma * 16 + g;
                if (ra < NN) {
                    float2 v = make_float2(acc[ma][na][0] + bb.x,
                                           acc[ma][na][1] + bb.y);
                    *(float2*)(o + (size_t)ra * CC + col) = v;
                }
                int rb = ra + 8;
                if (rb < NN) {
                    float2 v = make_float2(acc[ma][na][2] + bb.x,
                                           acc[ma][na][3] + bb.y);
                    *(float2*)(o + (size_t)rb * CC + col) = v;
                }
            }
        }
    }
}

// ---------------- fused attention + aggregation (warp per dst, no atomics) ---
// 2-edge unroll: two independent shuffle-reduce chains in flight (ILP=2).
__device__ __forceinline__ float leaky_dot(float4 a, float4 r, float4 t) {
    float4 m;
    m.x = a.x + r.x; m.x = m.x > 0.f ? m.x : NEG_SLOPE * m.x;
    m.y = a.y + r.y; m.y = m.y > 0.f ? m.y : NEG_SLOPE * m.y;
    m.z = a.z + r.z; m.z = m.z > 0.f ? m.z : NEG_SLOPE * m.z;
    m.w = a.w + r.w; m.w = m.w > 0.f ? m.w : NEG_SLOPE * m.w;
    float p = m.x * t.x;
    p = fmaf(m.y, t.y, p);
    p = fmaf(m.z, t.z, p);
    p = fmaf(m.w, t.w, p);
    return p;
}

__global__ __launch_bounds__(256) void aggr_kernel(
    const float* __restrict__ xl, const float* __restrict__ xr,
    const float* __restrict__ att, float* __restrict__ res_out)
{
    int gw   = (int)((blockIdx.x * 256u + threadIdx.x) >> 5);
    int lane = threadIdx.x & 31;
    if (gw >= NN) return;
    const int d = gw;

    float4 t = *(const float4*)(att + lane * 4);
    float4 r = *(const float4*)(xr + (size_t)d * CC + lane * 4);

    const int start = g_off[d];
    const int deg   = g_deg[d];          // >= 1 (self loop)

    float denom = 0.f;
    float4 acc = make_float4(0.f, 0.f, 0.f, 0.f);

    int jj = 0;
    for (; jj + 1 < deg; jj += 2) {
        int s0 = g_csr[start + jj];
        int s1 = g_csr[start + jj + 1];
        float4 a0 = *(const float4*)(xl + (size_t)s0 * CC + lane * 4);
        float4 a1 = *(const float4*)(xl + (size_t)s1 * CC + lane * 4);
        float p0 = leaky_dot(a0, r, t);
        float p1 = leaky_dot(a1, r, t);
#pragma unroll
        for (int off = 16; off > 0; off >>= 1) {
            p0 += __shfl_xor_sync(0xffffffffu, p0, off);
            p1 += __shfl_xor_sync(0xffffffffu, p1, off);
        }
        float ev0 = expf(p0);
        float ev1 = expf(p1);
        denom += ev0 + ev1;
        acc.x = fmaf(ev0, a0.x, fmaf(ev1, a1.x, acc.x));
        acc.y = fmaf(ev0, a0.y, fmaf(ev1, a1.y, acc.y));
        acc.z = fmaf(ev0, a0.z, fmaf(ev1, a1.z, acc.z));
        acc.w = fmaf(ev0, a0.w, fmaf(ev1, a1.w, acc.w));
    }
    if (jj < deg) {
        int s0 = g_csr[start + jj];
        float4 a0 = *(const float4*)(xl + (size_t)s0 * CC + lane * 4);
        float p0 = leaky_dot(a0, r, t);
#pragma unroll
        for (int off = 16; off > 0; off >>= 1)
            p0 += __shfl_xor_sync(0xffffffffu, p0, off);
        float ev0 = expf(p0);
        denom += ev0;
        acc.x = fmaf(ev0, a0.x, acc.x);
        acc.y = fmaf(ev0, a0.y, acc.y);
        acc.z = fmaf(ev0, a0.z, acc.z);
        acc.w = fmaf(ev0, a0.w, acc.w);
    }

    float inv = 1.f / denom;
    float* op = res_out + (size_t)d * CC + lane * 4;
    float4 rr = *(const float4*)op;
    float4 o = make_float4(fmaf(acc.x, inv, rr.x), fmaf(acc.y, inv, rr.y),
                           fmaf(acc.z, inv, rr.z), fmaf(acc.w, inv, rr.w));
    *(float4*)op = o;
}

// ---------------- launch ------------------------------------------------------
extern "C" void kernel_launch(void* const* d_in, const int* in_sizes, int n_in,
                              void* d_out, int out_size)
{
    const int*   ei    = (const int*)  d_in[0];
    const float* emb   = (const float*)d_in[1];
    const float* Wl1   = (const float*)d_in[2];
    const float* bl1   = (const float*)d_in[3];
    const float* Wr1   = (const float*)d_in[4];
    const float* br1   = (const float*)d_in[5];
    const float* att1  = (const float*)d_in[6];
    const float* Wres1 = (const float*)d_in[7];
    const float* bias1 = (const float*)d_in[8];
    const float* Wl2   = (const float*)d_in[9];
    const float* bl2   = (const float*)d_in[10];
    const float* Wr2   = (const float*)d_in[11];
    const float* br2   = (const float*)d_in[12];
    const float* att2  = (const float*)d_in[13];
    const float* Wres2 = (const float*)d_in[14];
    const float* bias2 = (const float*)d_in[15];
    float* out = (float*)d_out;

    float *xl, *xr, *h;
    __nv_bfloat16 *Wh, *Wl;
    int *deg, *cur;
    cudaGetSymbolAddress((void**)&xl,  g_xl);
    cudaGetSymbolAddress((void**)&xr,  g_xr);
    cudaGetSymbolAddress((void**)&h,   g_h);
    cudaGetSymbolAddress((void**)&Wh,  g_Wh);
    cudaGetSymbolAddress((void**)&Wl,  g_Wl);
    cudaGetSymbolAddress((void**)&deg, g_deg);
    cudaGetSymbolAddress((void**)&cur, g_cur);

    cudaFuncSetAttribute(gemm3_tc_kernel,
                         cudaFuncAttributeMaxDynamicSharedMemorySize, SM_TOTAL);

    const int edge_grid = (EP + 255) / 256;        // 2891
    const int gemm_grid = (NN + 127) / 128;        // 782
    const int aggr_grid = (NN * 32 + 255) / 256;   // 12500

    // Launch order chosen so ncu (-s 5 -c 1, memsets count) captures gemm3_tc.
    cudaMemsetAsync(deg, 0, NN * sizeof(int));                      // 0
    cudaMemsetAsync(cur, 0, NN * sizeof(int));                      // 1
    wsplit_kernel<<<(6 * CC * CC + 255) / 256, 256>>>(              // 2
        Wl1, Wr1, Wres1, Wl2, Wr2, Wres2);
    hist_kernel<<<edge_grid, 256>>>(ei);                            // 3
    scan1_kernel<<<NBLK, SCAN_BLK>>>();                             // 4
    gemm3_tc_kernel<<<gemm_grid, 256, SM_TOTAL>>>(                  // 5  <- profiled
        emb, Wh, Wl, 0, bl1, xl, br1, xr, bias1, h, 0);
    scan2_kernel<<<1, 128>>>();                                     // 6
    scan3_kernel<<<(NN + 255) / 256, 256>>>();                      // 7
    scatter_kernel<<<edge_grid, 256>>>(ei);                         // 8
    aggr_kernel<<<aggr_grid, 256>>>(xl, xr, att1, h);               // 9
    gemm3_tc_kernel<<<gemm_grid, 256, SM_TOTAL>>>(                  // 10
        h, Wh, Wl, 3, bl2, xl, br2, xr, bias2, out, 1);
    aggr_kernel<<<aggr_grid, 256>>>(xl, xr, att2, out);             // 11
}